// round 1
// baseline (speedup 1.0000x reference)
#include <cuda_runtime.h>
#include <cmath>

#define BB 128
#define LL 512
#define HH 512
#define TT 24
#define TAG_START 22
#define TAG_STOP  23

// Scratch: X[b,l,t] = exp(emit[b,l,t]).  128*512*24 floats = 6.3 MB (L2-resident).
__device__ float g_X[BB * LL * TT];

// ---------------------------------------------------------------------------
// Kernel 1: emission GEMM + exp.
// emit[row, t] = sum_h feat[row,h] * W[t,h] + bias[t];  X = exp(emit)
// One thread per (b,l) row; W staged in shared memory (24x512 fp32 = 48KB).
// ---------------------------------------------------------------------------
__global__ __launch_bounds__(256) void emit_kernel(
    const float* __restrict__ feat,
    const float* __restrict__ Wm,
    const float* __restrict__ bias)
{
    __shared__ float Wsh[TT][HH];  // exactly 48KB

    const int tid = threadIdx.x;

    // Cooperative load of W into shared (float4)
    const float4* Wv = reinterpret_cast<const float4*>(Wm);
    float4* Wshv = reinterpret_cast<float4*>(&Wsh[0][0]);
    #pragma unroll 4
    for (int i = tid; i < TT * HH / 4; i += 256) Wshv[i] = Wv[i];
    __syncthreads();

    const long row = (long)blockIdx.x * 256 + tid;   // 0..65535 exactly
    const float4* fp = reinterpret_cast<const float4*>(feat + row * (long)HH);

    float acc[TT];
    #pragma unroll
    for (int t = 0; t < TT; ++t) acc[t] = 0.f;

    #pragma unroll 2
    for (int h4 = 0; h4 < HH / 4; ++h4) {
        const float4 f = fp[h4];
        const float4* wp = reinterpret_cast<const float4*>(&Wsh[0][0]) + h4;
        #pragma unroll
        for (int t = 0; t < TT; ++t) {
            const float4 wv = wp[t * (HH / 4)];
            acc[t] = fmaf(f.x, wv.x, acc[t]);
            acc[t] = fmaf(f.y, wv.y, acc[t]);
            acc[t] = fmaf(f.z, wv.z, acc[t]);
            acc[t] = fmaf(f.w, wv.w, acc[t]);
        }
    }

    float res[TT];
    #pragma unroll
    for (int t = 0; t < TT; ++t) res[t] = __expf(acc[t] + bias[t]);

    float4* op = reinterpret_cast<float4*>(g_X + row * TT);  // row*24*4 bytes, 16B aligned
    #pragma unroll
    for (int i = 0; i < TT / 4; ++i)
        op[i] = reinterpret_cast<const float4*>(res)[i];
}

// ---------------------------------------------------------------------------
// Kernel 2: linear-domain CRF scan. One warp per batch element.
// State: lane j (j<24) owns w[j] (linear, power-of-2 normalized), plus a
// shared integer exponent Mexp. Step:
//   s[j]  = sum_k E[j][k] * w[k]          (E = exp(trans), rows in registers)
//   w'[j] = X[t][j] * s[j] * pending_scale
//   pending scale for NEXT step = 2^-(max_exponent(w')),  Mexp accumulates.
// Renormalization is pure ALU (exponent-field extraction via uint redux).
// ---------------------------------------------------------------------------
__global__ __launch_bounds__(256) void scan_kernel(
    const float* __restrict__ trans,
    const int*   __restrict__ lengths,
    float*       __restrict__ out)
{
    __shared__ float wsh[2][8][32];

    const int lane = threadIdx.x & 31;
    const int warp = threadIdx.x >> 5;
    const int b = blockIdx.x * 8 + warp;

    // E row for this lane: E[k] = exp(trans[lane][k]); lanes >= 24 hold zeros.
    float E[TT];
    #pragma unroll
    for (int k = 0; k < TT; ++k)
        E[k] = (lane < TT) ? __expf(trans[lane * TT + k]) : 0.f;
    // terminal transition: exp(trans[STOP][lane])
    const float TE = (lane < TT) ? __expf(trans[TAG_STOP * TT + lane]) : 0.f;

    const int len = lengths[b];                 // 1..512
    const float* Xb = g_X + (size_t)b * LL * TT;

    float w = (lane == TAG_START) ? 1.f : 0.f;  // exp of initial alphas
    int   Mexp  = 0;
    float scale = 1.f;
    int   dpend = 0;

    // Software-pipelined emission loads (depth 3; L2-resident)
    float x0 = (lane < TT) ? Xb[0 * TT + lane] : 0.f;
    float x1 = (lane < TT) ? Xb[1 * TT + lane] : 0.f;
    float x2 = (lane < TT) ? Xb[2 * TT + lane] : 0.f;

    int pp = 0;
    for (int t = 0; t < len; ++t) {
        wsh[pp][warp][lane] = w;

        // prefetch X for step t+3 (clamped to valid memory)
        int tp = t + 3; if (tp > LL - 1) tp = LL - 1;
        const float xn = (lane < TT) ? Xb[tp * TT + lane] : 0.f;

        __syncwarp();

        // matvec: s = E_row . w   (6 x float4 broadcast loads from shared)
        const float4* wv = reinterpret_cast<const float4*>(wsh[pp][warp]);
        float a0 = 0.f, a1 = 0.f, a2 = 0.f, a3 = 0.f;
        #pragma unroll
        for (int q = 0; q < 6; ++q) {
            const float4 v = wv[q];
            a0 = fmaf(E[4 * q + 0], v.x, a0);
            a1 = fmaf(E[4 * q + 1], v.y, a1);
            a2 = fmaf(E[4 * q + 2], v.z, a2);
            a3 = fmaf(E[4 * q + 3], v.w, a3);
        }
        const float s = (a0 + a1) + (a2 + a3);

        float wn = x0 * s * scale;   // apply pending normalization (lag-1)
        Mexp += dpend;
        if (lane >= TT) wn = 0.f;

        // exponent of max(wn) across lanes: wn >= 0 so raw bits are ordered
        const unsigned mb = __reduce_max_sync(0xffffffffu, __float_as_uint(wn));
        int e = (int)(mb >> 23);
        if (e == 0) {
            scale = 1.f; dpend = 0;       // degenerate (all ~0) guard
        } else {
            dpend = e - 127;
            scale = __uint_as_float((unsigned)(254 - e) << 23);  // 2^-(e-127)
        }

        w = wn;
        x0 = x1; x1 = x2; x2 = xn;
        pp ^= 1;
    }

    // apply the last pending normalization so that fv = ln(w) + Mexp*ln2
    w *= scale;
    Mexp += dpend;

    // alpha = log( sum_k w[k] * exp(trans[STOP][k]) ) + Mexp*ln2
    float term = w * TE;
    #pragma unroll
    for (int o = 16; o > 0; o >>= 1)
        term += __shfl_xor_sync(0xffffffffu, term, o);

    if (lane == 0)
        out[b] = __logf(term) + (float)Mexp * 0.69314718055994531f;
}

extern "C" void kernel_launch(void* const* d_in, const int* in_sizes, int n_in,
                              void* d_out, int out_size)
{
    const float* feat   = (const float*)d_in[0];  // [128,512,512]
    const float* Wm     = (const float*)d_in[1];  // [24,512]
    const float* bias   = (const float*)d_in[2];  // [24]
    const float* trans  = (const float*)d_in[3];  // [24,24]
    const int*   lens   = (const int*)d_in[4];    // [128]
    float* out = (float*)d_out;                   // [128]

    emit_kernel<<<256, 256>>>(feat, Wm, bias);
    scan_kernel<<<16, 256>>>(trans, lens, out);
}